// round 4
// baseline (speedup 1.0000x reference)
#include <cuda_runtime.h>
#include <cuda_bf16.h>
#include <stdint.h>
#include <math.h>

#define BATCH 4
#define SEQ   2048
#define NDIM  768
#define HDIM  768
#define MTOT  (BATCH * SEQ)

typedef __nv_bfloat16 bf16;

// ------------------------- scratch (allocation-free) ------------------------
__device__ __align__(16) bf16  g_xh[MTOT * NDIM];
__device__ __align__(16) bf16  g_xl[MTOT * NDIM];
__device__ __align__(16) bf16  g_wqh[HDIM * NDIM];
__device__ __align__(16) bf16  g_wql[HDIM * NDIM];
__device__ __align__(16) bf16  g_wkh[HDIM * NDIM];
__device__ __align__(16) bf16  g_wkl[HDIM * NDIM];
__device__ __align__(16) bf16  g_wvh[HDIM * NDIM];
__device__ __align__(16) bf16  g_wvl[HDIM * NDIM];
__device__ __align__(16) bf16  g_woh[NDIM * HDIM];
__device__ __align__(16) bf16  g_wol[NDIM * HDIM];
__device__ __align__(16) bf16  g_qh[MTOT * HDIM];
__device__ __align__(16) bf16  g_ql[MTOT * HDIM];
__device__ __align__(16) bf16  g_kh[MTOT * HDIM];
__device__ __align__(16) bf16  g_kl[MTOT * HDIM];
__device__ __align__(16) float g_v [MTOT * HDIM];
__device__ __align__(16) bf16  g_vth[(long long)BATCH * HDIM * SEQ];
__device__ __align__(16) bf16  g_vtl[(long long)BATCH * HDIM * SEQ];
__device__ __align__(16) float g_s [(long long)BATCH * SEQ * SEQ];
__device__ __align__(16) bf16  g_sh[(long long)BATCH * SEQ * SEQ];
__device__ __align__(16) bf16  g_sl[(long long)BATCH * SEQ * SEQ];
__device__ __align__(16) bf16  g_yh[MTOT * HDIM];
__device__ __align__(16) bf16  g_yl[MTOT * HDIM];

// ------------------------------ helpers -------------------------------------
__device__ __forceinline__ void mma16816(float* d, const uint32_t* a, const uint32_t* b)
{
    asm volatile(
        "mma.sync.aligned.m16n8k16.row.col.f32.bf16.bf16.f32 "
        "{%0,%1,%2,%3},{%4,%5,%6,%7},{%8,%9},{%0,%1,%2,%3};\n"
        : "+f"(d[0]), "+f"(d[1]), "+f"(d[2]), "+f"(d[3])
        : "r"(a[0]), "r"(a[1]), "r"(a[2]), "r"(a[3]), "r"(b[0]), "r"(b[1]));
}

__device__ __forceinline__ void split1(float x, bf16& h, bf16& l)
{
    h = __float2bfloat16(x);
    l = __float2bfloat16(x - __bfloat162float(h));
}

__device__ __forceinline__ void cpa16(uint32_t dst, const void* src)
{
    asm volatile("cp.async.cg.shared.global [%0], [%1], 16;\n" :: "r"(dst), "l"(src));
}
__device__ __forceinline__ void cpa_commit() { asm volatile("cp.async.commit_group;\n"); }
template <int N>
__device__ __forceinline__ void cpa_wait() { asm volatile("cp.async.wait_group %0;\n" :: "n"(N)); }

// smem geometry (uint32 words). Row = 16 data words (32 bf16 of k) + 4 pad.
#define RSTRIDE 20
#define PLANE_W (128 * RSTRIDE)           // 2560 words = 10240 B
#define STAGE_W (4 * PLANE_W)             // AsH AsL BsH BsL
#define STAGES  3
#define SMEM_BYTES (STAGES * STAGE_W * 4) // 122880

// ---------------------------------------------------------------------------
// Unified split-bf16 tensor-core GEMM: C = A * B^T (+bias)
//   A: [M,K] hi/lo bf16 planes, row-major
//   B: [N,K] hi/lo bf16 planes, row-major
// EPI = 0: write fp32 Cf.   EPI = 1: write split bf16 Ch/Cl.
// Block 128x128, BK=32, 8 warps of 64x32, 3-stage cp.async pipeline.
// Requires M%128==0, N%128==0, K%32==0.
// ---------------------------------------------------------------------------
template <int EPI>
__global__ void __launch_bounds__(256) bf16s_gemm(
    const bf16* __restrict__ Ah, const bf16* __restrict__ Al,
    const bf16* __restrict__ Bh, const bf16* __restrict__ Bl,
    const float* __restrict__ bias,
    float* __restrict__ Cf, bf16* __restrict__ Ch, bf16* __restrict__ Cl,
    int M, int N, int K,
    long long sA, long long sB, long long sC)
{
    extern __shared__ uint32_t smem[];

    Ah += (long long)blockIdx.z * sA;  Al += (long long)blockIdx.z * sA;
    Bh += (long long)blockIdx.z * sB;  Bl += (long long)blockIdx.z * sB;
    if (EPI == 0) Cf += (long long)blockIdx.z * sC;
    else { Ch += (long long)blockIdx.z * sC; Cl += (long long)blockIdx.z * sC; }

    const int tid  = threadIdx.x;
    const int lane = tid & 31;
    const int warp = tid >> 5;
    const int bm = blockIdx.y * 128;
    const int bn = blockIdx.x * 128;
    const int wm = (warp & 1) * 64;
    const int wn = (warp >> 1) * 32;
    const int r = lane >> 2;
    const int c = lane & 3;

    // loader mapping: thread -> row=tid/2, two 16B chunks per plane
    const int ld_row = tid >> 1;
    const int ld_c0  = (tid & 1) * 2;       // chunks c0, c0+1 (of 4)
    const bf16* pAh = Ah + (long long)(bm + ld_row) * K + ld_c0 * 8;
    const bf16* pAl = Al + (long long)(bm + ld_row) * K + ld_c0 * 8;
    const bf16* pBh = Bh + (long long)(bn + ld_row) * K + ld_c0 * 8;
    const bf16* pBl = Bl + (long long)(bn + ld_row) * K + ld_c0 * 8;

    uint32_t smem_u32;
    asm("{ .reg .u64 t; cvta.to.shared.u64 t, %1; cvt.u32.u64 %0, t; }"
        : "=r"(smem_u32) : "l"(smem));
    const uint32_t dst_base = smem_u32 + (ld_row * RSTRIDE + 4 * ld_c0) * 4;

    auto load_stage = [&](int stage, int k0) {
        const uint32_t d = dst_base + stage * (STAGE_W * 4);
        cpa16(d,                      pAh + k0);
        cpa16(d + 16,                 pAh + k0 + 8);
        cpa16(d + PLANE_W * 4,        pAl + k0);
        cpa16(d + PLANE_W * 4 + 16,   pAl + k0 + 8);
        cpa16(d + 2 * PLANE_W * 4,      pBh + k0);
        cpa16(d + 2 * PLANE_W * 4 + 16, pBh + k0 + 8);
        cpa16(d + 3 * PLANE_W * 4,      pBl + k0);
        cpa16(d + 3 * PLANE_W * 4 + 16, pBl + k0 + 8);
    };

    float acc[4][4][4];
    #pragma unroll
    for (int i = 0; i < 4; i++)
        #pragma unroll
        for (int j = 0; j < 4; j++)
            #pragma unroll
            for (int e = 0; e < 4; e++) acc[i][j][e] = 0.f;

    const int T = K / 32;

    // prologue: prefetch 2 stages
    load_stage(0, 0);  cpa_commit();
    load_stage(1, 32); cpa_commit();

    for (int t = 0; t < T; t++) {
        cpa_wait<1>();
        __syncthreads();

        // prefetch t+2
        if (t + 2 < T) load_stage((t + 2) % STAGES, (t + 2) * 32);
        cpa_commit();

        const uint32_t* AsH = smem + (t % STAGES) * STAGE_W;
        const uint32_t* AsL = AsH + PLANE_W;
        const uint32_t* BsH = AsH + 2 * PLANE_W;
        const uint32_t* BsL = AsH + 3 * PLANE_W;

        #pragma unroll
        for (int ks = 0; ks < 2; ks++) {
            const int col = 8 * ks + c;
            uint32_t aH[4][4], aL[4][4], bH[4][2], bL[4][2];
            #pragma unroll
            for (int mi = 0; mi < 4; mi++) {
                const int row = wm + mi * 16 + r;
                aH[mi][0] = AsH[row * RSTRIDE + col];
                aH[mi][1] = AsH[(row + 8) * RSTRIDE + col];
                aH[mi][2] = AsH[row * RSTRIDE + col + 4];
                aH[mi][3] = AsH[(row + 8) * RSTRIDE + col + 4];
                aL[mi][0] = AsL[row * RSTRIDE + col];
                aL[mi][1] = AsL[(row + 8) * RSTRIDE + col];
                aL[mi][2] = AsL[row * RSTRIDE + col + 4];
                aL[mi][3] = AsL[(row + 8) * RSTRIDE + col + 4];
            }
            #pragma unroll
            for (int ni = 0; ni < 4; ni++) {
                const int n = wn + ni * 8 + r;
                bH[ni][0] = BsH[n * RSTRIDE + col];
                bH[ni][1] = BsH[n * RSTRIDE + col + 4];
                bL[ni][0] = BsL[n * RSTRIDE + col];
                bL[ni][1] = BsL[n * RSTRIDE + col + 4];
            }
            #pragma unroll
            for (int mi = 0; mi < 4; mi++)
                #pragma unroll
                for (int ni = 0; ni < 4; ni++) {
                    mma16816(acc[mi][ni], aH[mi], bH[ni]);
                    mma16816(acc[mi][ni], aH[mi], bL[ni]);
                    mma16816(acc[mi][ni], aL[mi], bH[ni]);
                }
        }
        __syncthreads();
    }

    // ---------------- epilogue ----------------
    #pragma unroll
    for (int mi = 0; mi < 4; mi++)
        #pragma unroll
        for (int ni = 0; ni < 4; ni++) {
            const int row = bm + wm + mi * 16 + r;
            const int col = bn + wn + ni * 8 + 2 * c;
            float v00 = acc[mi][ni][0], v01 = acc[mi][ni][1];
            float v10 = acc[mi][ni][2], v11 = acc[mi][ni][3];
            if (bias) {
                const float b0 = bias[col], b1 = bias[col + 1];
                v00 += b0; v01 += b1; v10 += b0; v11 += b1;
            }
            if (EPI == 0) {
                *reinterpret_cast<float2*>(Cf + (long long)row * N + col)
                    = make_float2(v00, v01);
                *reinterpret_cast<float2*>(Cf + (long long)(row + 8) * N + col)
                    = make_float2(v10, v11);
            } else {
                bf16 h0, l0, h1, l1;
                split1(v00, h0, l0); split1(v01, h1, l1);
                *reinterpret_cast<__nv_bfloat162*>(Ch + (long long)row * N + col)
                    = __halves2bfloat162(h0, h1);
                *reinterpret_cast<__nv_bfloat162*>(Cl + (long long)row * N + col)
                    = __halves2bfloat162(l0, l1);
                split1(v10, h0, l0); split1(v11, h1, l1);
                *reinterpret_cast<__nv_bfloat162*>(Ch + (long long)(row + 8) * N + col)
                    = __halves2bfloat162(h0, h1);
                *reinterpret_cast<__nv_bfloat162*>(Cl + (long long)(row + 8) * N + col)
                    = __halves2bfloat162(l0, l1);
            }
        }
}

// ---------------------------------------------------------------------------
// Elementwise fp32 -> hi/lo bf16 split (vectorized, grid-stride)
// ---------------------------------------------------------------------------
__global__ void __launch_bounds__(256) split_f32(
    const float* __restrict__ in, bf16* __restrict__ h, bf16* __restrict__ l, int n4)
{
    for (int i = blockIdx.x * blockDim.x + threadIdx.x; i < n4;
         i += gridDim.x * blockDim.x) {
        float4 v = reinterpret_cast<const float4*>(in)[i];
        bf16 h0,l0,h1,l1,h2,l2,h3,l3;
        split1(v.x, h0, l0); split1(v.y, h1, l1);
        split1(v.z, h2, l2); split1(v.w, h3, l3);
        __nv_bfloat162 hv0 = __halves2bfloat162(h0, h1);
        __nv_bfloat162 hv1 = __halves2bfloat162(h2, h3);
        __nv_bfloat162 lv0 = __halves2bfloat162(l0, l1);
        __nv_bfloat162 lv1 = __halves2bfloat162(l2, l3);
        reinterpret_cast<__nv_bfloat162*>(h)[2 * i]     = hv0;
        reinterpret_cast<__nv_bfloat162*>(h)[2 * i + 1] = hv1;
        reinterpret_cast<__nv_bfloat162*>(l)[2 * i]     = lv0;
        reinterpret_cast<__nv_bfloat162*>(l)[2 * i + 1] = lv1;
    }
}

// ---------------------------------------------------------------------------
// V transpose + split: V [B*SEQ, HDIM] fp32 -> VT [B, HDIM, SEQ] hi/lo bf16
// ---------------------------------------------------------------------------
__global__ void __launch_bounds__(256) transpose_split(
    const float* __restrict__ V, bf16* __restrict__ Th, bf16* __restrict__ Tl)
{
    __shared__ float tile[32][33];
    const int b  = blockIdx.z;
    const int h0 = blockIdx.x * 32;
    const int s0 = blockIdx.y * 32;
    const int tx = threadIdx.x & 31;
    const int ty = threadIdx.x >> 5;     // 0..7

    #pragma unroll
    for (int j = 0; j < 4; j++) {
        const int s = s0 + ty + j * 8;
        tile[ty + j * 8][tx] = V[(long long)(b * SEQ + s) * HDIM + h0 + tx];
    }
    __syncthreads();
    #pragma unroll
    for (int j = 0; j < 4; j++) {
        const int h = h0 + ty + j * 8;
        const float v = tile[tx][ty + j * 8];
        bf16 hi, lo; split1(v, hi, lo);
        const long long o = ((long long)b * HDIM + h) * SEQ + s0 + tx;
        Th[o] = hi; Tl[o] = lo;
    }
}

// ---------------------------------------------------------------------------
// Row softmax (2048 cols) reading fp32 scores, emitting hi/lo bf16 probs.
// ---------------------------------------------------------------------------
__global__ void __launch_bounds__(256) softmax_split(
    const float* __restrict__ S, bf16* __restrict__ Ph, bf16* __restrict__ Pl)
{
    __shared__ float buf[SEQ];
    __shared__ float red[8];

    const int tid = threadIdx.x;
    const float2* row2 = reinterpret_cast<const float2*>(S + (long long)blockIdx.x * SEQ);
    float2* b2 = reinterpret_cast<float2*>(buf);

    float m = -1e30f;
    #pragma unroll
    for (int j = 0; j < 4; j++) {
        float2 f = row2[tid + j * 256];
        b2[tid + j * 256] = f;
        m = fmaxf(m, fmaxf(f.x, f.y));
    }
    #pragma unroll
    for (int o = 16; o > 0; o >>= 1)
        m = fmaxf(m, __shfl_xor_sync(0xffffffffu, m, o));
    if ((tid & 31) == 0) red[tid >> 5] = m;
    __syncthreads();
    float bmax = red[0];
    #pragma unroll
    for (int w = 1; w < 8; w++) bmax = fmaxf(bmax, red[w]);
    __syncthreads();

    float s = 0.f;
    #pragma unroll
    for (int j = 0; j < 4; j++) {
        float2 f = b2[tid + j * 256];
        f.x = __expf(f.x - bmax);
        f.y = __expf(f.y - bmax);
        b2[tid + j * 256] = f;
        s += f.x + f.y;
    }
    #pragma unroll
    for (int o = 16; o > 0; o >>= 1)
        s += __shfl_xor_sync(0xffffffffu, s, o);
    if ((tid & 31) == 0) red[tid >> 5] = s;
    __syncthreads();
    float tot = 0.f;
    #pragma unroll
    for (int w = 0; w < 8; w++) tot += red[w];
    const float inv = 1.f / tot;

    __nv_bfloat162* ph2 = reinterpret_cast<__nv_bfloat162*>(Ph) + (long long)blockIdx.x * (SEQ / 2);
    __nv_bfloat162* pl2 = reinterpret_cast<__nv_bfloat162*>(Pl) + (long long)blockIdx.x * (SEQ / 2);
    #pragma unroll
    for (int j = 0; j < 4; j++) {
        float2 f = b2[tid + j * 256];
        const float p0 = f.x * inv, p1 = f.y * inv;
        bf16 h0,l0,h1,l1;
        split1(p0, h0, l0); split1(p1, h1, l1);
        ph2[tid + j * 256] = __halves2bfloat162(h0, h1);
        pl2[tid + j * 256] = __halves2bfloat162(l0, l1);
    }
}

// ---------------------------------------------------------------------------
extern "C" void kernel_launch(void* const* d_in, const int* in_sizes, int n_in,
                              void* d_out, int out_size)
{
    const float* x  = (const float*)d_in[0];
    const float* wq = (const float*)d_in[1];
    const float* bq = (const float*)d_in[2];
    const float* wk = (const float*)d_in[3];
    const float* bk = (const float*)d_in[4];
    const float* wv = (const float*)d_in[5];
    const float* bv = (const float*)d_in[6];
    const float* wo = (const float*)d_in[7];
    const float* bo = (const float*)d_in[8];
    float* out = (float*)d_out;

    static bool attr_done = false;
    if (!attr_done) {
        cudaFuncSetAttribute(bf16s_gemm<0>, cudaFuncAttributeMaxDynamicSharedMemorySize, SMEM_BYTES);
        cudaFuncSetAttribute(bf16s_gemm<1>, cudaFuncAttributeMaxDynamicSharedMemorySize, SMEM_BYTES);
        attr_done = true;
    }

    bf16 *xh,*xl,*wqh,*wql,*wkh,*wkl,*wvh,*wvl,*woh,*wol;
    bf16 *qh,*ql,*kh,*kl,*vth,*vtl,*sh,*sl,*yh,*yl;
    float *v, *s;
    cudaGetSymbolAddress((void**)&xh, g_xh);   cudaGetSymbolAddress((void**)&xl, g_xl);
    cudaGetSymbolAddress((void**)&wqh, g_wqh); cudaGetSymbolAddress((void**)&wql, g_wql);
    cudaGetSymbolAddress((void**)&wkh, g_wkh); cudaGetSymbolAddress((void**)&wkl, g_wkl);
    cudaGetSymbolAddress((void**)&wvh, g_wvh); cudaGetSymbolAddress((void**)&wvl, g_wvl);
    cudaGetSymbolAddress((void**)&woh, g_woh); cudaGetSymbolAddress((void**)&wol, g_wol);
    cudaGetSymbolAddress((void**)&qh, g_qh);   cudaGetSymbolAddress((void**)&ql, g_ql);
    cudaGetSymbolAddress((void**)&kh, g_kh);   cudaGetSymbolAddress((void**)&kl, g_kl);
    cudaGetSymbolAddress((void**)&v, g_v);
    cudaGetSymbolAddress((void**)&vth, g_vth); cudaGetSymbolAddress((void**)&vtl, g_vtl);
    cudaGetSymbolAddress((void**)&s, g_s);
    cudaGetSymbolAddress((void**)&sh, g_sh);   cudaGetSymbolAddress((void**)&sl, g_sl);
    cudaGetSymbolAddress((void**)&yh, g_yh);   cudaGetSymbolAddress((void**)&yl, g_yl);

    const dim3 blk(256);

    // 0) split x and weights
    split_f32<<<512, blk>>>(x,  xh,  xl,  MTOT * NDIM / 4);
    split_f32<<<128, blk>>>(wq, wqh, wql, HDIM * NDIM / 4);
    split_f32<<<128, blk>>>(wk, wkh, wkl, HDIM * NDIM / 4);
    split_f32<<<128, blk>>>(wv, wvh, wvl, HDIM * NDIM / 4);
    split_f32<<<128, blk>>>(wo, woh, wol, NDIM * HDIM / 4);

    // 1) projections: q,k -> split bf16; v -> fp32 (then transpose+split)
    {
        dim3 grid(HDIM / 128, MTOT / 128, 1);
        bf16s_gemm<1><<<grid, blk, SMEM_BYTES>>>(xh, xl, wqh, wql, bq,
                                                 nullptr, qh, ql, MTOT, HDIM, NDIM, 0, 0, 0);
        bf16s_gemm<1><<<grid, blk, SMEM_BYTES>>>(xh, xl, wkh, wkl, bk,
                                                 nullptr, kh, kl, MTOT, HDIM, NDIM, 0, 0, 0);
        bf16s_gemm<0><<<grid, blk, SMEM_BYTES>>>(xh, xl, wvh, wvl, bv,
                                                 v, nullptr, nullptr, MTOT, HDIM, NDIM, 0, 0, 0);
    }
    {
        dim3 grid(HDIM / 32, SEQ / 32, BATCH);
        transpose_split<<<grid, blk>>>(v, vth, vtl);
    }

    // 2) scores = Q K^T (fp32 out)
    {
        dim3 grid(SEQ / 128, SEQ / 128, BATCH);
        bf16s_gemm<0><<<grid, blk, SMEM_BYTES>>>(qh, ql, kh, kl, nullptr,
                                                 s, nullptr, nullptr, SEQ, SEQ, HDIM,
                                                 (long long)SEQ * HDIM,
                                                 (long long)SEQ * HDIM,
                                                 (long long)SEQ * SEQ);
    }

    // 3) softmax -> split bf16 probs
    softmax_split<<<BATCH * SEQ, blk>>>(s, sh, sl);

    // 4) y = P V  (B operand = V^T [HDIM, SEQ]) -> split bf16
    {
        dim3 grid(HDIM / 128, SEQ / 128, BATCH);
        bf16s_gemm<1><<<grid, blk, SMEM_BYTES>>>(sh, sl, vth, vtl, nullptr,
                                                 nullptr, yh, yl, SEQ, HDIM, SEQ,
                                                 (long long)SEQ * SEQ,
                                                 (long long)HDIM * SEQ,
                                                 (long long)SEQ * HDIM);
    }

    // 5) out = Y Wo^T + bo (fp32 out)
    {
        dim3 grid(NDIM / 128, MTOT / 128, 1);
        bf16s_gemm<0><<<grid, blk, SMEM_BYTES>>>(yh, yl, woh, wol, bo,
                                                 out, nullptr, nullptr, MTOT, NDIM, HDIM, 0, 0, 0);
    }
}

// round 5
// speedup vs baseline: 1.1764x; 1.1764x over previous
#include <cuda_runtime.h>
#include <cuda_bf16.h>
#include <stdint.h>
#include <math.h>

#define BATCH 4
#define SEQ   2048
#define NDIM  768
#define HDIM  768
#define MTOT  (BATCH * SEQ)

typedef __nv_bfloat16 bf16;

// ------------------------- scratch (allocation-free) ------------------------
__device__ __align__(16) bf16  g_xh[MTOT * NDIM];
__device__ __align__(16) bf16  g_xl[MTOT * NDIM];
__device__ __align__(16) bf16  g_wqh[HDIM * NDIM];
__device__ __align__(16) bf16  g_wql[HDIM * NDIM];
__device__ __align__(16) bf16  g_wkh[HDIM * NDIM];
__device__ __align__(16) bf16  g_wkl[HDIM * NDIM];
__device__ __align__(16) bf16  g_wvh[HDIM * NDIM];
__device__ __align__(16) bf16  g_wvl[HDIM * NDIM];
__device__ __align__(16) bf16  g_woh[NDIM * HDIM];
__device__ __align__(16) bf16  g_wol[NDIM * HDIM];
__device__ __align__(16) bf16  g_qh[MTOT * HDIM];
__device__ __align__(16) bf16  g_ql[MTOT * HDIM];
__device__ __align__(16) bf16  g_kh[MTOT * HDIM];
__device__ __align__(16) bf16  g_kl[MTOT * HDIM];
__device__ __align__(16) float g_v [MTOT * HDIM];
__device__ __align__(16) bf16  g_vth[(long long)BATCH * HDIM * SEQ];
__device__ __align__(16) bf16  g_vtl[(long long)BATCH * HDIM * SEQ];
__device__ __align__(16) float g_s [(long long)BATCH * SEQ * SEQ];
__device__ __align__(16) bf16  g_sh[(long long)BATCH * SEQ * SEQ];
__device__ __align__(16) bf16  g_sl[(long long)BATCH * SEQ * SEQ];
__device__ __align__(16) bf16  g_yh[MTOT * HDIM];
__device__ __align__(16) bf16  g_yl[MTOT * HDIM];

// ------------------------------ helpers -------------------------------------
__device__ __forceinline__ void mma16816(float* d, const uint32_t* a, const uint32_t* b)
{
    asm volatile(
        "mma.sync.aligned.m16n8k16.row.col.f32.bf16.bf16.f32 "
        "{%0,%1,%2,%3},{%4,%5,%6,%7},{%8,%9},{%0,%1,%2,%3};\n"
        : "+f"(d[0]), "+f"(d[1]), "+f"(d[2]), "+f"(d[3])
        : "r"(a[0]), "r"(a[1]), "r"(a[2]), "r"(a[3]), "r"(b[0]), "r"(b[1]));
}

__device__ __forceinline__ void ldsm_x4(uint32_t* r, uint32_t addr)
{
    asm volatile("ldmatrix.sync.aligned.m8n8.x4.shared.b16 {%0,%1,%2,%3}, [%4];"
                 : "=r"(r[0]), "=r"(r[1]), "=r"(r[2]), "=r"(r[3]) : "r"(addr));
}
__device__ __forceinline__ void ldsm_x2(uint32_t* r, uint32_t addr)
{
    asm volatile("ldmatrix.sync.aligned.m8n8.x2.shared.b16 {%0,%1}, [%2];"
                 : "=r"(r[0]), "=r"(r[1]) : "r"(addr));
}

__device__ __forceinline__ void split1(float x, bf16& h, bf16& l)
{
    h = __float2bfloat16(x);
    l = __float2bfloat16(x - __bfloat162float(h));
}

__device__ __forceinline__ void cpa16(uint32_t dst, const void* src)
{
    asm volatile("cp.async.cg.shared.global [%0], [%1], 16;\n" :: "r"(dst), "l"(src));
}
__device__ __forceinline__ void cpa_commit() { asm volatile("cp.async.commit_group;\n"); }
template <int N>
__device__ __forceinline__ void cpa_wait() { asm volatile("cp.async.wait_group %0;\n" :: "n"(N)); }

// smem geometry (uint32 words). Row = 16 data words (32 bf16 of k) + 4 pad.
#define RSTRIDE 20
#define PLANE_W (128 * RSTRIDE)              // 2560 words = 10240 B
#define PLANE_B (PLANE_W * 4)
#define STAGE_W (4 * PLANE_W)                // AsH AsL BsH BsL
#define STAGE_B (STAGE_W * 4)                // 40960 B
#define STAGES  2
#define SMEM_BYTES (STAGES * STAGE_B)        // 81920

// ---------------------------------------------------------------------------
// Unified split-bf16 tensor-core GEMM: C = A * B^T (+bias)
//   A: [M,K] hi/lo bf16 planes; B: [N,K] hi/lo bf16 planes (row-major)
// EPI=0: fp32 Cf.  EPI=1: split bf16 Ch/Cl.
// Block 128x128, BK=32, 8 warps of 64x32, 2-stage cp.async, ldmatrix frags.
// ---------------------------------------------------------------------------
template <int EPI>
__global__ void __launch_bounds__(256, 2) bf16s_gemm(
    const bf16* __restrict__ Ah, const bf16* __restrict__ Al,
    const bf16* __restrict__ Bh, const bf16* __restrict__ Bl,
    const float* __restrict__ bias,
    float* __restrict__ Cf, bf16* __restrict__ Ch, bf16* __restrict__ Cl,
    int M, int N, int K,
    long long sA, long long sB, long long sC)
{
    extern __shared__ uint32_t smem[];

    Ah += (long long)blockIdx.z * sA;  Al += (long long)blockIdx.z * sA;
    Bh += (long long)blockIdx.z * sB;  Bl += (long long)blockIdx.z * sB;
    if (EPI == 0) Cf += (long long)blockIdx.z * sC;
    else { Ch += (long long)blockIdx.z * sC; Cl += (long long)blockIdx.z * sC; }

    const int tid  = threadIdx.x;
    const int lane = tid & 31;
    const int warp = tid >> 5;
    const int bm = blockIdx.y * 128;
    const int bn = blockIdx.x * 128;
    const int wm = (warp & 1) * 64;
    const int wn = (warp >> 1) * 32;
    const int r = lane >> 2;
    const int c = lane & 3;

    // ---- loader mapping: thread -> row=tid/2, two 16B chunks per plane ----
    const int ld_row = tid >> 1;
    const int ld_c0  = (tid & 1) * 2;
    const bf16* pAh = Ah + (long long)(bm + ld_row) * K + ld_c0 * 8;
    const bf16* pAl = Al + (long long)(bm + ld_row) * K + ld_c0 * 8;
    const bf16* pBh = Bh + (long long)(bn + ld_row) * K + ld_c0 * 8;
    const bf16* pBl = Bl + (long long)(bn + ld_row) * K + ld_c0 * 8;

    uint32_t smem_u32;
    asm("{ .reg .u64 t; cvta.to.shared.u64 t, %1; cvt.u32.u64 %0, t; }"
        : "=r"(smem_u32) : "l"(smem));
    const uint32_t dst_base = smem_u32 + (ld_row * RSTRIDE + 4 * ld_c0) * 4;

    auto load_stage = [&](int stage, int k0) {
        const uint32_t d = dst_base + stage * STAGE_B;
        cpa16(d,                pAh + k0);
        cpa16(d + 16,           pAh + k0 + 8);
        cpa16(d + PLANE_B,      pAl + k0);
        cpa16(d + PLANE_B + 16, pAl + k0 + 8);
        cpa16(d + 2 * PLANE_B,      pBh + k0);
        cpa16(d + 2 * PLANE_B + 16, pBh + k0 + 8);
        cpa16(d + 3 * PLANE_B,      pBl + k0);
        cpa16(d + 3 * PLANE_B + 16, pBl + k0 + 8);
    };

    // ---- ldmatrix lane addresses (within a stage/plane) ----
    // A .x4: lanes 0-7 rows m..m+7 @k0 | 8-15 rows m+8..15 @k0
    //        | 16-23 rows m..m+7 @k+8 | 24-31 rows m+8..15 @k+8
    const uint32_t aOff = (((wm + (lane & 15)) * RSTRIDE + ((lane >> 4) << 2)) << 2);
    // B .x2: lanes 0-7 rows n..n+7 @k0 | 8-15 rows n..n+7 @k+8
    const uint32_t bOff = (((wn + (lane & 7)) * RSTRIDE + (((lane >> 3) & 1) << 2)) << 2);

    float acc[4][4][4];
    #pragma unroll
    for (int i = 0; i < 4; i++)
        #pragma unroll
        for (int j = 0; j < 4; j++)
            #pragma unroll
            for (int e = 0; e < 4; e++) acc[i][j][e] = 0.f;

    const int T = K / 32;

    load_stage(0, 0);  cpa_commit();
    if (T > 1) load_stage(1, 32);
    cpa_commit();

    for (int t = 0; t < T; t++) {
        cpa_wait<1>();
        __syncthreads();

        const uint32_t stage_base = smem_u32 + (t & 1) * STAGE_B;
        const uint32_t aBaseH = stage_base + aOff;
        const uint32_t aBaseL = aBaseH + PLANE_B;
        const uint32_t bBaseH = stage_base + 2 * PLANE_B + bOff;
        const uint32_t bBaseL = bBaseH + PLANE_B;

        #pragma unroll
        for (int ks = 0; ks < 2; ks++) {
            const uint32_t kb = ks * 32;   // 8 words
            uint32_t aH[4][4], aL[4][4], bH[4][2], bL[4][2];
            #pragma unroll
            for (int mi = 0; mi < 4; mi++) {
                ldsm_x4(aH[mi], aBaseH + mi * (16 * RSTRIDE * 4) + kb);
                ldsm_x4(aL[mi], aBaseL + mi * (16 * RSTRIDE * 4) + kb);
            }
            #pragma unroll
            for (int ni = 0; ni < 4; ni++) {
                ldsm_x2(bH[ni], bBaseH + ni * (8 * RSTRIDE * 4) + kb);
                ldsm_x2(bL[ni], bBaseL + ni * (8 * RSTRIDE * 4) + kb);
            }
            #pragma unroll
            for (int mi = 0; mi < 4; mi++)
                #pragma unroll
                for (int ni = 0; ni < 4; ni++) {
                    mma16816(acc[mi][ni], aH[mi], bH[ni]);
                    mma16816(acc[mi][ni], aH[mi], bL[ni]);
                    mma16816(acc[mi][ni], aL[mi], bH[ni]);
                }
        }
        __syncthreads();

        if (t + 2 < T) load_stage(t & 1, (t + 2) * 32);
        cpa_commit();
    }

    // ---------------- epilogue ----------------
    #pragma unroll
    for (int mi = 0; mi < 4; mi++)
        #pragma unroll
        for (int ni = 0; ni < 4; ni++) {
            const int row = bm + wm + mi * 16 + r;
            const int col = bn + wn + ni * 8 + 2 * c;
            float v00 = acc[mi][ni][0], v01 = acc[mi][ni][1];
            float v10 = acc[mi][ni][2], v11 = acc[mi][ni][3];
            if (bias) {
                const float b0 = bias[col], b1 = bias[col + 1];
                v00 += b0; v01 += b1; v10 += b0; v11 += b1;
            }
            if (EPI == 0) {
                *reinterpret_cast<float2*>(Cf + (long long)row * N + col)
                    = make_float2(v00, v01);
                *reinterpret_cast<float2*>(Cf + (long long)(row + 8) * N + col)
                    = make_float2(v10, v11);
            } else {
                bf16 h0, l0, h1, l1;
                split1(v00, h0, l0); split1(v01, h1, l1);
                *reinterpret_cast<__nv_bfloat162*>(Ch + (long long)row * N + col)
                    = __halves2bfloat162(h0, h1);
                *reinterpret_cast<__nv_bfloat162*>(Cl + (long long)row * N + col)
                    = __halves2bfloat162(l0, l1);
                split1(v10, h0, l0); split1(v11, h1, l1);
                *reinterpret_cast<__nv_bfloat162*>(Ch + (long long)(row + 8) * N + col)
                    = __halves2bfloat162(h0, h1);
                *reinterpret_cast<__nv_bfloat162*>(Cl + (long long)(row + 8) * N + col)
                    = __halves2bfloat162(l0, l1);
            }
        }
}

// ---------------------------------------------------------------------------
__global__ void __launch_bounds__(256) split_f32(
    const float* __restrict__ in, bf16* __restrict__ h, bf16* __restrict__ l, int n4)
{
    for (int i = blockIdx.x * blockDim.x + threadIdx.x; i < n4;
         i += gridDim.x * blockDim.x) {
        float4 v = reinterpret_cast<const float4*>(in)[i];
        bf16 h0,l0,h1,l1,h2,l2,h3,l3;
        split1(v.x, h0, l0); split1(v.y, h1, l1);
        split1(v.z, h2, l2); split1(v.w, h3, l3);
        reinterpret_cast<__nv_bfloat162*>(h)[2 * i]     = __halves2bfloat162(h0, h1);
        reinterpret_cast<__nv_bfloat162*>(h)[2 * i + 1] = __halves2bfloat162(h2, h3);
        reinterpret_cast<__nv_bfloat162*>(l)[2 * i]     = __halves2bfloat162(l0, l1);
        reinterpret_cast<__nv_bfloat162*>(l)[2 * i + 1] = __halves2bfloat162(l2, l3);
    }
}

// ---------------------------------------------------------------------------
// V transpose + split: V [B*SEQ, HDIM] fp32 -> VT [B, HDIM, SEQ] hi/lo bf16
// ---------------------------------------------------------------------------
__global__ void __launch_bounds__(256) transpose_split(
    const float* __restrict__ V, bf16* __restrict__ Th, bf16* __restrict__ Tl)
{
    __shared__ float tile[32][33];
    const int b  = blockIdx.z;
    const int h0 = blockIdx.x * 32;
    const int s0 = blockIdx.y * 32;
    const int tx = threadIdx.x & 31;
    const int ty = threadIdx.x >> 5;

    #pragma unroll
    for (int j = 0; j < 4; j++) {
        const int s = s0 + ty + j * 8;
        tile[ty + j * 8][tx] = V[(long long)(b * SEQ + s) * HDIM + h0 + tx];
    }
    __syncthreads();
    #pragma unroll
    for (int j = 0; j < 4; j++) {
        const int h = h0 + ty + j * 8;
        const float v = tile[tx][ty + j * 8];
        bf16 hi, lo; split1(v, hi, lo);
        const long long o = ((long long)b * HDIM + h) * SEQ + s0 + tx;
        Th[o] = hi; Tl[o] = lo;
    }
}

// ---------------------------------------------------------------------------
__global__ void __launch_bounds__(256) softmax_split(
    const float* __restrict__ S, bf16* __restrict__ Ph, bf16* __restrict__ Pl)
{
    __shared__ float buf[SEQ];
    __shared__ float red[8];

    const int tid = threadIdx.x;
    const float2* row2 = reinterpret_cast<const float2*>(S + (long long)blockIdx.x * SEQ);
    float2* b2 = reinterpret_cast<float2*>(buf);

    float m = -1e30f;
    #pragma unroll
    for (int j = 0; j < 4; j++) {
        float2 f = row2[tid + j * 256];
        b2[tid + j * 256] = f;
        m = fmaxf(m, fmaxf(f.x, f.y));
    }
    #pragma unroll
    for (int o = 16; o > 0; o >>= 1)
        m = fmaxf(m, __shfl_xor_sync(0xffffffffu, m, o));
    if ((tid & 31) == 0) red[tid >> 5] = m;
    __syncthreads();
    float bmax = red[0];
    #pragma unroll
    for (int w = 1; w < 8; w++) bmax = fmaxf(bmax, red[w]);
    __syncthreads();

    float s = 0.f;
    #pragma unroll
    for (int j = 0; j < 4; j++) {
        float2 f = b2[tid + j * 256];
        f.x = __expf(f.x - bmax);
        f.y = __expf(f.y - bmax);
        b2[tid + j * 256] = f;
        s += f.x + f.y;
    }
    #pragma unroll
    for (int o = 16; o > 0; o >>= 1)
        s += __shfl_xor_sync(0xffffffffu, s, o);
    if ((tid & 31) == 0) red[tid >> 5] = s;
    __syncthreads();
    float tot = 0.f;
    #pragma unroll
    for (int w = 0; w < 8; w++) tot += red[w];
    const float inv = 1.f / tot;

    __nv_bfloat162* ph2 = reinterpret_cast<__nv_bfloat162*>(Ph) + (long long)blockIdx.x * (SEQ / 2);
    __nv_bfloat162* pl2 = reinterpret_cast<__nv_bfloat162*>(Pl) + (long long)blockIdx.x * (SEQ / 2);
    #pragma unroll
    for (int j = 0; j < 4; j++) {
        float2 f = b2[tid + j * 256];
        const float p0 = f.x * inv, p1 = f.y * inv;
        bf16 h0,l0,h1,l1;
        split1(p0, h0, l0); split1(p1, h1, l1);
        ph2[tid + j * 256] = __halves2bfloat162(h0, h1);
        pl2[tid + j * 256] = __halves2bfloat162(l0, l1);
    }
}

// ---------------------------------------------------------------------------
extern "C" void kernel_launch(void* const* d_in, const int* in_sizes, int n_in,
                              void* d_out, int out_size)
{
    const float* x  = (const float*)d_in[0];
    const float* wq = (const float*)d_in[1];
    const float* bq = (const float*)d_in[2];
    const float* wk = (const float*)d_in[3];
    const float* bk = (const float*)d_in[4];
    const float* wv = (const float*)d_in[5];
    const float* bv = (const float*)d_in[6];
    const float* wo = (const float*)d_in[7];
    const float* bo = (const float*)d_in[8];
    float* out = (float*)d_out;

    static bool attr_done = false;
    if (!attr_done) {
        cudaFuncSetAttribute(bf16s_gemm<0>, cudaFuncAttributeMaxDynamicSharedMemorySize, SMEM_BYTES);
        cudaFuncSetAttribute(bf16s_gemm<1>, cudaFuncAttributeMaxDynamicSharedMemorySize, SMEM_BYTES);
        attr_done = true;
    }

    bf16 *xh,*xl,*wqh,*wql,*wkh,*wkl,*wvh,*wvl,*woh,*wol;
    bf16 *qh,*ql,*kh,*kl,*vth,*vtl,*sh,*sl,*yh,*yl;
    float *v, *s;
    cudaGetSymbolAddress((void**)&xh, g_xh);   cudaGetSymbolAddress((void**)&xl, g_xl);
    cudaGetSymbolAddress((void**)&wqh, g_wqh); cudaGetSymbolAddress((void**)&wql, g_wql);
    cudaGetSymbolAddress((void**)&wkh, g_wkh); cudaGetSymbolAddress((void**)&wkl, g_wkl);
    cudaGetSymbolAddress((void**)&wvh, g_wvh); cudaGetSymbolAddress((void**)&wvl, g_wvl);
    cudaGetSymbolAddress((void**)&woh, g_woh); cudaGetSymbolAddress((void**)&wol, g_wol);
    cudaGetSymbolAddress((void**)&qh, g_qh);   cudaGetSymbolAddress((void**)&ql, g_ql);
    cudaGetSymbolAddress((void**)&kh, g_kh);   cudaGetSymbolAddress((void**)&kl, g_kl);
    cudaGetSymbolAddress((void**)&v, g_v);
    cudaGetSymbolAddress((void**)&vth, g_vth); cudaGetSymbolAddress((void**)&vtl, g_vtl);
    cudaGetSymbolAddress((void**)&s, g_s);
    cudaGetSymbolAddress((void**)&sh, g_sh);   cudaGetSymbolAddress((void**)&sl, g_sl);
    cudaGetSymbolAddress((void**)&yh, g_yh);   cudaGetSymbolAddress((void**)&yl, g_yl);

    const dim3 blk(256);

    // 0) split x and weights
    split_f32<<<512, blk>>>(x,  xh,  xl,  MTOT * NDIM / 4);
    split_f32<<<128, blk>>>(wq, wqh, wql, HDIM * NDIM / 4);
    split_f32<<<128, blk>>>(wk, wkh, wkl, HDIM * NDIM / 4);
    split_f32<<<128, blk>>>(wv, wvh, wvl, HDIM * NDIM / 4);
    split_f32<<<128, blk>>>(wo, woh, wol, NDIM * HDIM / 4);

    // 1) projections
    {
        dim3 grid(HDIM / 128, MTOT / 128, 1);
        bf16s_gemm<1><<<grid, blk, SMEM_BYTES>>>(xh, xl, wqh, wql, bq,
                                                 nullptr, qh, ql, MTOT, HDIM, NDIM, 0, 0, 0);
        bf16s_gemm<1><<<grid, blk, SMEM_BYTES>>>(xh, xl, wkh, wkl, bk,
                                                 nullptr, kh, kl, MTOT, HDIM, NDIM, 0, 0, 0);
        bf16s_gemm<0><<<grid, blk, SMEM_BYTES>>>(xh, xl, wvh, wvl, bv,
                                                 v, nullptr, nullptr, MTOT, HDIM, NDIM, 0, 0, 0);
    }
    {
        dim3 grid(HDIM / 32, SEQ / 32, BATCH);
        transpose_split<<<grid, blk>>>(v, vth, vtl);
    }

    // 2) scores = Q K^T
    {
        dim3 grid(SEQ / 128, SEQ / 128, BATCH);
        bf16s_gemm<0><<<grid, blk, SMEM_BYTES>>>(qh, ql, kh, kl, nullptr,
                                                 s, nullptr, nullptr, SEQ, SEQ, HDIM,
                                                 (long long)SEQ * HDIM,
                                                 (long long)SEQ * HDIM,
                                                 (long long)SEQ * SEQ);
    }

    // 3) softmax -> split bf16 probs
    softmax_split<<<BATCH * SEQ, blk>>>(s, sh, sl);

    // 4) y = P V^T(B operand)
    {
        dim3 grid(HDIM / 128, SEQ / 128, BATCH);
        bf16s_gemm<1><<<grid, blk, SMEM_BYTES>>>(sh, sl, vth, vtl, nullptr,
                                                 nullptr, yh, yl, SEQ, HDIM, SEQ,
                                                 (long long)SEQ * SEQ,
                                                 (long long)HDIM * SEQ,
                                                 (long long)SEQ * HDIM);
    }

    // 5) out = Y Wo^T + bo
    {
        dim3 grid(NDIM / 128, MTOT / 128, 1);
        bf16s_gemm<0><<<grid, blk, SMEM_BYTES>>>(yh, yl, woh, wol, bo,
                                                 out, nullptr, nullptr, MTOT, NDIM, HDIM, 0, 0, 0);
    }
}